// round 1
// baseline (speedup 1.0000x reference)
#include <cuda_runtime.h>

#define RES 1024
#define NUM_ROOMS 8
#define N_AGENTS 5000000
#define PLANE (RES * RES)

// Scratch (no device allocation allowed): separable Gaussian tables + max bits.
__device__ float g_ex[NUM_ROOMS * RES];   // exp(-(x_i - cx_r)^2 / (2 sx^2))
__device__ float g_ey[NUM_ROOMS * RES];   // exp(-(y_j - cy_r)^2 / (2 sy^2))
__device__ int   g_maxbits;

// ---------------------------------------------------------------------------
// Kernel 1: zero the flow-field region of out, build ex/ey tables, reset max.
// ---------------------------------------------------------------------------
__global__ void k_init(const float* __restrict__ rooms, float* __restrict__ flow) {
    int tid = blockIdx.x * blockDim.x + threadIdx.x;
    if (tid < PLANE) flow[tid] = 0.0f;

    if (tid < NUM_ROOMS * RES) {
        int r = tid >> 10, i = tid & (RES - 1);
        float lin = (float)i * (1.0f / (RES - 1));
        float c = rooms[r * 4 + 0];
        float s = rooms[r * 4 + 2];
        float d = lin - c;
        g_ex[tid] = __expf(-d * d / (2.0f * s * s));
    } else if (tid < 2 * NUM_ROOMS * RES) {
        int t = tid - NUM_ROOMS * RES;
        int r = t >> 10, j = t & (RES - 1);
        float lin = (float)j * (1.0f / (RES - 1));
        float c = rooms[r * 4 + 1];
        float s = rooms[r * 4 + 3];
        float d = lin - c;
        g_ey[t] = __expf(-d * d / (2.0f * s * s));
    }
    if (tid == 0) g_maxbits = 0;
}

// ---------------------------------------------------------------------------
// Kernel 2: histogram of agent positions into flow (atomic float add).
// ---------------------------------------------------------------------------
__global__ void k_hist(const float2* __restrict__ pos, float* __restrict__ flow, int n) {
    int tid = blockIdx.x * blockDim.x + threadIdx.x;
    if (tid >= n) return;
    float2 p = pos[tid];
    int ix = (int)(p.x * (float)RES);
    int iy = (int)(p.y * (float)RES);
    ix = min(max(ix, 0), RES - 1);
    iy = min(max(iy, 0), RES - 1);
    atomicAdd(&flow[(ix << 10) | iy], 1.0f);
}

// ---------------------------------------------------------------------------
// Kernel 3: global max of flow (float4 loads, warp+block reduce, int atomicMax
// — valid because all values are >= 0).
// ---------------------------------------------------------------------------
__global__ void k_max(const float* __restrict__ flow) {
    __shared__ float smax[8];
    int tid = blockIdx.x * blockDim.x + threadIdx.x;   // PLANE/4 threads total
    const float4* f4 = (const float4*)flow;
    float4 v = f4[tid];
    float m = fmaxf(fmaxf(v.x, v.y), fmaxf(v.z, v.w));
    #pragma unroll
    for (int off = 16; off > 0; off >>= 1)
        m = fmaxf(m, __shfl_xor_sync(0xffffffffu, m, off));
    int lane = threadIdx.x & 31, warp = threadIdx.x >> 5;
    if (lane == 0) smax[warp] = m;
    __syncthreads();
    if (threadIdx.x == 0) {
        float bm = smax[0];
        #pragma unroll
        for (int w = 1; w < 8; w++) bm = fmaxf(bm, smax[w]);
        atomicMax(&g_maxbits, __float_as_int(bm));
    }
}

// ---------------------------------------------------------------------------
// Kernel 4: normalize flow in place; write 8 dynamic-layout planes using the
// separable Gaussian tables.
// ---------------------------------------------------------------------------
__global__ void k_final(const float* __restrict__ wall, float* __restrict__ out) {
    int idx = blockIdx.x * blockDim.x + threadIdx.x;   // < PLANE
    float* flow = out + NUM_ROOMS * PLANE;

    float mx = __int_as_float(g_maxbits);
    float inv = 1.0f / (mx + 1e-6f);

    int i = idx >> 10, j = idx & (RES - 1);
    float f = flow[idx];
    flow[idx] = f * inv;

    float w = 1.0f - wall[idx];
    #pragma unroll
    for (int r = 0; r < NUM_ROOMS; r++) {
        out[r * PLANE + idx] = g_ex[(r << 10) + i] * g_ey[(r << 10) + j] * w;
    }
}

// ---------------------------------------------------------------------------
extern "C" void kernel_launch(void* const* d_in, const int* in_sizes, int n_in,
                              void* d_out, int out_size) {
    const float* pos   = (const float*)d_in[0];   // [5000000, 2]
    const float* rooms = (const float*)d_in[1];   // [8, 4]
    const float* wall  = (const float*)d_in[2];   // [1024, 1024]
    float* out = (float*)d_out;                   // [8*1024*1024 + 1024*1024]
    float* flow = out + NUM_ROOMS * PLANE;

    // 1) init: PLANE threads cover zeroing + table build
    k_init<<<(PLANE + 255) / 256, 256>>>(rooms, flow);

    // 2) histogram: one thread per agent
    k_hist<<<(N_AGENTS + 255) / 256, 256>>>((const float2*)pos, flow, N_AGENTS);

    // 3) max reduce: PLANE/4 threads, float4 each
    k_max<<<(PLANE / 4) / 256, 256>>>(flow);

    // 4) normalize + layout planes
    k_final<<<(PLANE + 255) / 256, 256>>>(wall, out);
}

// round 2
// speedup vs baseline: 1.0107x; 1.0107x over previous
#include <cuda_runtime.h>

#define RES 1024
#define NUM_ROOMS 8
#define N_AGENTS 5000000
#define PLANE (RES * RES)

// Scratch (no device allocation allowed): separable Gaussian tables + max bits.
__device__ __align__(16) float g_ex[NUM_ROOMS * RES];  // exp(-(x_i-cx)^2/(2sx^2))
__device__ __align__(16) float g_ey[NUM_ROOMS * RES];  // exp(-(y_j-cy)^2/(2sy^2))
__device__ int g_maxbits;

// ---------------------------------------------------------------------------
// Kernel 1: zero flow region (float4), build ex/ey tables, reset max.
// grid covers PLANE/4 threads.
// ---------------------------------------------------------------------------
__global__ void k_init(const float* __restrict__ rooms, float4* __restrict__ flow4) {
    int tid = blockIdx.x * blockDim.x + threadIdx.x;
    if (tid < PLANE / 4) flow4[tid] = make_float4(0.f, 0.f, 0.f, 0.f);

    if (tid < NUM_ROOMS * RES) {
        int r = tid >> 10, i = tid & (RES - 1);
        float lin = (float)i * (1.0f / (RES - 1));
        float cx = rooms[r * 4 + 0], sx = rooms[r * 4 + 2];
        float cy = rooms[r * 4 + 1], sy = rooms[r * 4 + 3];
        float dx = lin - cx;
        float dy = lin - cy;
        g_ex[tid] = __expf(-dx * dx / (2.0f * sx * sx));
        g_ey[tid] = __expf(-dy * dy / (2.0f * sy * sy));
    }
    if (tid == 0) g_maxbits = 0;
}

// ---------------------------------------------------------------------------
// Kernel 2: histogram. float4 load = 2 agents per thread. RED.ADD.F32 scatter.
// ---------------------------------------------------------------------------
__global__ void k_hist(const float4* __restrict__ pos4, float* __restrict__ flow, int npairs) {
    int tid = blockIdx.x * blockDim.x + threadIdx.x;
    if (tid >= npairs) return;
    float4 p = pos4[tid];

    int ix0 = min(max((int)(p.x * (float)RES), 0), RES - 1);
    int iy0 = min(max((int)(p.y * (float)RES), 0), RES - 1);
    int ix1 = min(max((int)(p.z * (float)RES), 0), RES - 1);
    int iy1 = min(max((int)(p.w * (float)RES), 0), RES - 1);

    atomicAdd(&flow[(ix0 << 10) | iy0], 1.0f);
    atomicAdd(&flow[(ix1 << 10) | iy1], 1.0f);
}

// ---------------------------------------------------------------------------
// Kernel 3: global max of flow. Grid-stride float4, warp+block reduce,
// int atomicMax (valid: counts >= 0).
// ---------------------------------------------------------------------------
__global__ void k_max(const float4* __restrict__ flow4) {
    __shared__ float smax[8];
    float m = 0.0f;
    int stride = gridDim.x * blockDim.x;
    for (int t = blockIdx.x * blockDim.x + threadIdx.x; t < PLANE / 4; t += stride) {
        float4 v = flow4[t];
        m = fmaxf(m, fmaxf(fmaxf(v.x, v.y), fmaxf(v.z, v.w)));
    }
    #pragma unroll
    for (int off = 16; off > 0; off >>= 1)
        m = fmaxf(m, __shfl_xor_sync(0xffffffffu, m, off));
    int lane = threadIdx.x & 31, warp = threadIdx.x >> 5;
    if (lane == 0) smax[warp] = m;
    __syncthreads();
    if (threadIdx.x == 0) {
        float bm = smax[0];
        #pragma unroll
        for (int w = 1; w < 8; w++) bm = fmaxf(bm, smax[w]);
        atomicMax(&g_maxbits, __float_as_int(bm));
    }
}

// ---------------------------------------------------------------------------
// Kernel 4: one block per row i; each thread handles 4 consecutive j.
// Normalize flow in place; write 8 layout planes, all as float4.
// ---------------------------------------------------------------------------
__global__ void __launch_bounds__(256) k_final(const float4* __restrict__ wall4,
                                               float* __restrict__ out) {
    int i = blockIdx.x;                 // row
    int q = threadIdx.x;                // float4 index within row, 0..255
    int idx4 = (i << 8) + q;            // float4 index into a plane
    float4* out4 = (float4*)out;
    float4* flow4 = out4 + NUM_ROOMS * (PLANE / 4);

    float inv = 1.0f / (__int_as_float(g_maxbits) + 1e-6f);

    // normalize flow
    float4 f = flow4[idx4];
    f.x *= inv; f.y *= inv; f.z *= inv; f.w *= inv;
    flow4[idx4] = f;

    // wall factor
    float4 w = wall4[idx4];
    w.x = 1.0f - w.x; w.y = 1.0f - w.y; w.z = 1.0f - w.z; w.w = 1.0f - w.w;

    const float4* ey4 = (const float4*)g_ey;
    #pragma unroll
    for (int r = 0; r < NUM_ROOMS; r++) {
        float ex = g_ex[(r << 10) + i];          // uniform per block
        float4 e = ey4[(r << 8) + q];            // 4 consecutive j
        float4 o;
        o.x = ex * e.x * w.x;
        o.y = ex * e.y * w.y;
        o.z = ex * e.z * w.z;
        o.w = ex * e.w * w.w;
        out4[r * (PLANE / 4) + idx4] = o;
    }
}

// ---------------------------------------------------------------------------
extern "C" void kernel_launch(void* const* d_in, const int* in_sizes, int n_in,
                              void* d_out, int out_size) {
    const float* pos   = (const float*)d_in[0];   // [5000000, 2]
    const float* rooms = (const float*)d_in[1];   // [8, 4]
    const float* wall  = (const float*)d_in[2];   // [1024, 1024]
    float* out = (float*)d_out;                   // 8 planes + flow plane
    float* flow = out + NUM_ROOMS * PLANE;

    // 1) init: PLANE/4 threads cover zeroing; first 8192 also build tables
    k_init<<<(PLANE / 4 + 255) / 256, 256>>>(rooms, (float4*)flow);

    // 2) histogram: 2 agents per thread (float4 position loads)
    int npairs = N_AGENTS / 2;   // 2,500,000
    k_hist<<<(npairs + 255) / 256, 256>>>((const float4*)pos, flow, npairs);

    // 3) max reduce: grid-stride float4
    k_max<<<1184, 256>>>((const float4*)flow);

    // 4) normalize + 8 layout planes, fully vectorized
    k_final<<<RES, 256>>>((const float4*)wall, out);
}